// round 8
// baseline (speedup 1.0000x reference)
#include <cuda_runtime.h>
#include <cstdint>
#include <math_constants.h>

// Shape-specialized constants
#define LQ   256
#define HKV  2
#define HQN  32
#define GPH  16
#define DIM  128
#define SSEL 16
#define BS   64

#define NTHREADS 128
// stage0(K 1024 + V 1024 f4) + stage1(K+V) + Q(512 f4) = 4608 float4 = 73728 B
#define SMEM_BYTES (4608 * 16)

__device__ __forceinline__ void cp16(void* smem_dst, const void* gmem_src) {
    uint32_t a = (uint32_t)__cvta_generic_to_shared(smem_dst);
    asm volatile("cp.async.cg.shared.global [%0], [%1], 16;" :: "r"(a), "l"(gmem_src));
}
__device__ __forceinline__ void ffma2(unsigned long long& d, unsigned long long a,
                                      unsigned long long b) {
    asm("fma.rn.f32x2 %0, %1, %2, %0;" : "+l"(d) : "l"(a), "l"(b));
}
__device__ __forceinline__ unsigned long long splat2(float x) {
    unsigned long long r;
    asm("mov.b64 %0, {%1, %1};" : "=l"(r) : "f"(x));
    return r;
}
__device__ __forceinline__ float hadd2(unsigned long long v) {
    float lo, hi;
    asm("mov.b64 {%0, %1}, %2;" : "=f"(lo), "=f"(hi) : "l"(v));
    return lo + hi;
}
__device__ __forceinline__ float2 unpack2(unsigned long long v) {
    float2 f;
    asm("mov.b64 {%0, %1}, %2;" : "=f"(f.x), "=f"(f.y) : "l"(v));
    return f;
}

__global__ __launch_bounds__(NTHREADS, 3)
void hsa_prefill_kernel(const float* __restrict__ q,
                        const float* __restrict__ k,
                        const float* __restrict__ v,
                        const float* __restrict__ w,
                        const int*   __restrict__ bidx,
                        float* __restrict__ out)
{
    extern __shared__ float4 sm4[];
    // stage p: K at p*2048, V at p*2048+1024 (each 32 rows x 32 f4 chunks, XOR-swizzled)
    float4* Q4 = sm4 + 4096;   // 16 head rows x 32 chunks, linear

    const int t    = threadIdx.x;
    const int lane = t & 31;
    const int wid  = t >> 5;           // warp owns heads g = 4*wid .. 4*wid+3
    const int l    = (int)blockIdx.x >> 1;
    const int h    = (int)blockIdx.x & 1;
    const int sw   = lane & 7;         // swizzle key: local row == lane in both halves

    // ---- Q tile: 16 head rows for this (l, h) ----
    const float4* qg = (const float4*)(q + ((size_t)l*HQN + h*GPH) * DIM);
    #pragma unroll
    for (int ci = t; ci < 512; ci += NTHREADS) Q4[ci] = qg[ci];

    const float sm_scale = 0.08838834764831844f;  // 1/sqrt(128)

    unsigned long long oAcc[4][2] = {};

    const int*   bi = bidx + ((size_t)l*HKV + h) * SSEL;
    const float* wp = w + ((size_t)l*HQN + h*GPH + 4*wid) * SSEL;

    // prefetch helper (issues 16 cp16 + commit for one 32-key half)
    auto prefetch = [&](int stage, int idx, int halfBase) {
        const float* kb = k + ((size_t)(idx*BS + halfBase)*HKV + h) * DIM;
        const float* vb = v + ((size_t)(idx*BS + halfBase)*HKV + h) * DIM;
        float4* Kst = sm4 + stage*2048;
        float4* Vst = Kst + 1024;
        #pragma unroll
        for (int r = 0; r < 8; ++r) {
            int ci = t + (r << 7);            // 0..1023
            int u = ci >> 5, c = ci & 31;     // local row, chunk
            int dci = (u << 5) | (c ^ (u & 7));
            const size_t off = (size_t)u*(HKV*DIM) + c*4;
            cp16(&Kst[dci], kb + off);
            cp16(&Vst[dci], vb + off);
        }
        asm volatile("cp.async.commit_group;");
    };

    {
        int idx0 = __ldg(bi + 0); if (idx0 < 0) idx0 = 0;
        prefetch(0, idx0, 0);      // group: stage0 = half0 of block 0
        prefetch(1, idx0, 32);     // group: stage1 = half1 of block 0
    }

    #pragma unroll 1
    for (int s = 0; s < SSEL; ++s) {
        const int rawidx = __ldg(bi + s);
        const float validf = (rawidx >= 0) ? 1.0f : 0.0f;
        int nidx = 0;
        if (s + 1 < SSEL) { nidx = __ldg(bi + s + 1); if (nidx < 0) nidx = 0; }

        unsigned long long sAcc[4][2] = {};
        const float4* Qb = Q4 + (wid << 7);

        // ---- wait stage0 (half0), QK on K0: scores for u = lane ----
        asm volatile("cp.async.wait_group 1;");
        __syncthreads();
        {
            const float4* Krow = sm4 + (lane << 5);
            #pragma unroll 8
            for (int c = 0; c < 32; ++c) {
                const int cs = c ^ sw;
                const ulonglong2 k0 = *(const ulonglong2*)&Krow[cs];
                #pragma unroll
                for (int g = 0; g < 4; ++g) {
                    const ulonglong2 qq = *(const ulonglong2*)&Qb[(g << 5) + c];
                    ffma2(sAcc[g][0], qq.x, k0.x);
                    ffma2(sAcc[g][0], qq.y, k0.y);
                }
            }
        }

        // ---- wait stage1 (half1), QK on K1: scores for u = lane+32 ----
        asm volatile("cp.async.wait_group 0;");
        __syncthreads();
        {
            const float4* Krow = sm4 + 2048 + (lane << 5);
            #pragma unroll 8
            for (int c = 0; c < 32; ++c) {
                const int cs = c ^ sw;
                const ulonglong2 k1 = *(const ulonglong2*)&Krow[cs];
                #pragma unroll
                for (int g = 0; g < 4; ++g) {
                    const ulonglong2 qq = *(const ulonglong2*)&Qb[(g << 5) + c];
                    ffma2(sAcc[g][1], qq.x, k1.x);
                    ffma2(sAcc[g][1], qq.y, k1.y);
                }
            }
        }

        // ---- per-block softmax over 64 keys (full-warp reductions) ----
        float ev[4][2];
        #pragma unroll
        for (int g = 0; g < 4; ++g) {
            float s0 = hadd2(sAcc[g][0]) * sm_scale;
            float s1 = hadd2(sAcc[g][1]) * sm_scale;
            float m = fmaxf(s0, s1);
            #pragma unroll
            for (int o = 16; o; o >>= 1)
                m = fmaxf(m, __shfl_xor_sync(0xffffffffu, m, o));
            float e0 = __expf(s0 - m), e1 = __expf(s1 - m);
            float sum = e0 + e1;
            #pragma unroll
            for (int o = 16; o; o >>= 1)
                sum += __shfl_xor_sync(0xffffffffu, sum, o);
            const float coef = validf * __fdividef(__ldg(wp + g*SSEL + s), sum);
            ev[g][0] = e0 * coef;
            ev[g][1] = e1 * coef;
        }

        // ---- overlay P on stage1's K region (dead after QK1) ----
        __syncthreads();                         // all warps done reading K1
        float4* Pw = sm4 + 2048 + (wid << 6);    // per-warp 64-entry P[u]
        Pw[lane]      = make_float4(ev[0][0], ev[1][0], ev[2][0], ev[3][0]);
        Pw[lane + 32] = make_float4(ev[0][1], ev[1][1], ev[2][1], ev[3][1]);
        __syncwarp();                            // own-warp P visible

        // ---- PV half0 (u = 0..31) from stage0 V ----
        {
            const float4* Vst = sm4 + 1024;
            #pragma unroll 8
            for (int u = 0; u < 32; ++u) {
                const float4 p4 = Pw[u];
                const ulonglong2 vv =
                    *(const ulonglong2*)&Vst[(u << 5) | (lane ^ (u & 7))];
                unsigned long long p;
                p = splat2(p4.x); ffma2(oAcc[0][0], vv.x, p); ffma2(oAcc[0][1], vv.y, p);
                p = splat2(p4.y); ffma2(oAcc[1][0], vv.x, p); ffma2(oAcc[1][1], vv.y, p);
                p = splat2(p4.z); ffma2(oAcc[2][0], vv.x, p); ffma2(oAcc[2][1], vv.y, p);
                p = splat2(p4.w); ffma2(oAcc[3][0], vv.x, p); ffma2(oAcc[3][1], vv.y, p);
            }
        }
        __syncthreads();                         // stage0 (K0+V0) fully consumed
        if (s + 1 < SSEL) prefetch(0, nidx, 0);  // overlap with PV1

        // ---- PV half1 (u = 32..63) from stage1 V ----
        {
            const float4* Vst = sm4 + 3072;
            #pragma unroll 8
            for (int u = 32; u < 64; ++u) {
                const float4 p4 = Pw[u];
                const ulonglong2 vv =
                    *(const ulonglong2*)&Vst[((u & 31) << 5) | (lane ^ (u & 7))];
                unsigned long long p;
                p = splat2(p4.x); ffma2(oAcc[0][0], vv.x, p); ffma2(oAcc[0][1], vv.y, p);
                p = splat2(p4.y); ffma2(oAcc[1][0], vv.x, p); ffma2(oAcc[1][1], vv.y, p);
                p = splat2(p4.z); ffma2(oAcc[2][0], vv.x, p); ffma2(oAcc[2][1], vv.y, p);
                p = splat2(p4.w); ffma2(oAcc[3][0], vv.x, p); ffma2(oAcc[3][1], vv.y, p);
            }
        }
        __syncthreads();                         // stage1 (V1 + P overlay) consumed
        if (s + 1 < SSEL) prefetch(1, nidx, 32); // overlap with next QK0
    }

    // ---- write output: o[l, h*16 + 4*wid + g, 4*lane .. 4*lane+3] ----
    #pragma unroll
    for (int g = 0; g < 4; ++g) {
        const float2 lo = unpack2(oAcc[g][0]);
        const float2 hi = unpack2(oAcc[g][1]);
        float4* op = (float4*)(out + ((size_t)l*HQN + h*GPH + 4*wid + g) * DIM);
        op[lane] = make_float4(lo.x, lo.y, hi.x, hi.y);
    }
}

extern "C" void kernel_launch(void* const* d_in, const int* in_sizes, int n_in,
                              void* d_out, int out_size)
{
    (void)in_sizes; (void)n_in; (void)out_size;
    const float* q    = (const float*)d_in[0];
    const float* k    = (const float*)d_in[1];
    const float* v    = (const float*)d_in[2];
    const float* w    = (const float*)d_in[3];
    const int*   bidx = (const int*)d_in[4];
    float* out = (float*)d_out;

    static bool attr_set = false;
    if (!attr_set) {
        cudaFuncSetAttribute(hsa_prefill_kernel,
                             cudaFuncAttributeMaxDynamicSharedMemorySize, SMEM_BYTES);
        attr_set = true;
    }

    dim3 grid(LQ * HKV);
    dim3 block(NTHREADS);
    hsa_prefill_kernel<<<grid, block, SMEM_BYTES>>>(q, k, v, w, bidx, out);
}

// round 11
// speedup vs baseline: 1.0388x; 1.0388x over previous
#include <cuda_runtime.h>
#include <cstdint>
#include <math_constants.h>

// Shape-specialized constants
#define LQ   256
#define HKV  2
#define HQN  32
#define GPH  16
#define DIM  128
#define SSEL 16
#define BS   64

#define NTHREADS 128
// A(1024 f4) + B(1024) + Q(512) + P(256) = 2816 float4 = 45056 B
#define SMEM_BYTES (2816 * 16)

__device__ __forceinline__ void cp16(void* smem_dst, const void* gmem_src) {
    uint32_t a = (uint32_t)__cvta_generic_to_shared(smem_dst);
    asm volatile("cp.async.cg.shared.global [%0], [%1], 16;" :: "r"(a), "l"(gmem_src));
}
__device__ __forceinline__ void ffma2(unsigned long long& d, unsigned long long a,
                                      unsigned long long b) {
    asm("fma.rn.f32x2 %0, %1, %2, %0;" : "+l"(d) : "l"(a), "l"(b));
}
__device__ __forceinline__ unsigned long long splat2(float x) {
    unsigned long long r;
    asm("mov.b64 %0, {%1, %1};" : "=l"(r) : "f"(x));
    return r;
}
__device__ __forceinline__ float hadd2(unsigned long long v) {
    float lo, hi;
    asm("mov.b64 {%0, %1}, %2;" : "=f"(lo), "=f"(hi) : "l"(v));
    return lo + hi;
}
__device__ __forceinline__ float2 unpack2(unsigned long long v) {
    float2 f;
    asm("mov.b64 {%0, %1}, %2;" : "=f"(f.x), "=f"(f.y) : "l"(v));
    return f;
}

__global__ __launch_bounds__(NTHREADS, 4)
void hsa_prefill_kernel(const float* __restrict__ q,
                        const float* __restrict__ k,
                        const float* __restrict__ v,
                        const float* __restrict__ w,
                        const int*   __restrict__ bidx,
                        float* __restrict__ out)
{
    extern __shared__ float4 sm4[];
    float4* A4 = sm4;            // 32 rows x 32 chunks, XOR-swizzled (16 KB)
    float4* B4 = sm4 + 1024;     // same (16 KB)
    float4* Q4 = sm4 + 2048;     // 16 head rows x 32 chunks, linear (8 KB)
    float4* P4 = sm4 + 2560;     // 4 warps x 64 entries (4 KB)

    const int t    = threadIdx.x;
    const int lane = t & 31;
    const int wid  = t >> 5;           // warp owns heads g = 4*wid .. 4*wid+3
    const int l    = (int)blockIdx.x >> 1;
    const int h    = (int)blockIdx.x & 1;
    const int sw   = lane & 7;

    // ---- Q tile ----
    const float4* qg = (const float4*)(q + ((size_t)l*HQN + h*GPH) * DIM);
    #pragma unroll
    for (int ci = t; ci < 512; ci += NTHREADS) Q4[ci] = qg[ci];

    const float sm_scale = 0.08838834764831844f;  // 1/sqrt(128)

    unsigned long long oAcc[4][2] = {};

    const int*   bi = bidx + ((size_t)l*HKV + h) * SSEL;
    const float* wp = w + ((size_t)l*HQN + h*GPH + 4*wid) * SSEL;

    // issue one 16KB half-tensor load (32 rows x 128 floats) + commit
    auto loadHalf = [&](float4* dst, const float* srcRow0) {
        #pragma unroll
        for (int r = 0; r < 8; ++r) {
            int ci = t + (r << 7);            // 0..1023
            int u = ci >> 5, c = ci & 31;
            int dci = (u << 5) | (c ^ (u & 7));
            cp16(&dst[dci], srcRow0 + (size_t)u*(HKV*DIM) + c*4);
        }
        asm volatile("cp.async.commit_group;");
    };

    // prologue: K.0 of block 0 into A
    {
        int i0 = __ldg(bi + 0); if (i0 < 0) i0 = 0;
        loadHalf(A4, k + ((size_t)(i0*BS)*HKV + h) * DIM);
    }

    const float4* Qb = Q4 + (wid << 7);
    float4* Pw = P4 + (wid << 6);

    #pragma unroll 1
    for (int s = 0; s < SSEL; ++s) {
        const int rawidx = __ldg(bi + s);
        const float validf = (rawidx >= 0) ? 1.0f : 0.0f;
        int idx = rawidx < 0 ? 0 : rawidx;
        int nidx = 0;
        if (s + 1 < SSEL) { nidx = __ldg(bi + s + 1); if (nidx < 0) nidx = 0; }

        const float* kb = k + ((size_t)(idx*BS)*HKV + h) * DIM;
        const float* vb = v + ((size_t)(idx*BS)*HKV + h) * DIM;
        const size_t halfOff = (size_t)32*(HKV*DIM);

        unsigned long long sAcc[4][2] = {};

        // ---- phase 1: wait K.0 (A); issue K.1 -> B; QK.0 ----
        asm volatile("cp.async.wait_group 0;");
        __syncthreads();
        loadHalf(B4, kb + halfOff);
        {
            const float4* Krow = A4 + (lane << 5);
            #pragma unroll 4
            for (int c = 0; c < 32; ++c) {
                const int cs = c ^ sw;
                const ulonglong2 k0 = *(const ulonglong2*)&Krow[cs];
                #pragma unroll
                for (int g = 0; g < 4; ++g) {
                    const ulonglong2 qq = *(const ulonglong2*)&Qb[(g << 5) + c];
                    ffma2(sAcc[g][0], qq.x, k0.x);
                    ffma2(sAcc[g][0], qq.y, k0.y);
                }
            }
        }

        // ---- phase 2: wait K.1 (B); issue V.0 -> A; QK.1 ----
        asm volatile("cp.async.wait_group 0;");
        __syncthreads();
        loadHalf(A4, vb);
        {
            const float4* Krow = B4 + (lane << 5);
            #pragma unroll 4
            for (int c = 0; c < 32; ++c) {
                const int cs = c ^ sw;
                const ulonglong2 k1 = *(const ulonglong2*)&Krow[cs];
                #pragma unroll
                for (int g = 0; g < 4; ++g) {
                    const ulonglong2 qq = *(const ulonglong2*)&Qb[(g << 5) + c];
                    ffma2(sAcc[g][1], qq.x, k1.x);
                    ffma2(sAcc[g][1], qq.y, k1.y);
                }
            }
        }

        // ---- phase 3: softmax (overlaps V.0 flight); wait V.0; issue V.1 -> B; PV.0
        {
            float ev[4][2];
            #pragma unroll
            for (int g = 0; g < 4; ++g) {
                float s0 = hadd2(sAcc[g][0]) * sm_scale;
                float s1 = hadd2(sAcc[g][1]) * sm_scale;
                float m = fmaxf(s0, s1);
                #pragma unroll
                for (int o = 16; o; o >>= 1)
                    m = fmaxf(m, __shfl_xor_sync(0xffffffffu, m, o));
                float e0 = __expf(s0 - m), e1 = __expf(s1 - m);
                float sum = e0 + e1;
                #pragma unroll
                for (int o = 16; o; o >>= 1)
                    sum += __shfl_xor_sync(0xffffffffu, sum, o);
                const float coef = validf * __fdividef(__ldg(wp + g*SSEL + s), sum);
                ev[g][0] = e0 * coef;
                ev[g][1] = e1 * coef;
            }
            Pw[lane]      = make_float4(ev[0][0], ev[1][0], ev[2][0], ev[3][0]);
            Pw[lane + 32] = make_float4(ev[0][1], ev[1][1], ev[2][1], ev[3][1]);
            __syncwarp();
        }
        asm volatile("cp.async.wait_group 0;");
        __syncthreads();
        loadHalf(B4, vb + halfOff);
        {
            #pragma unroll 4
            for (int u = 0; u < 32; ++u) {
                const float4 p4 = Pw[u];
                const ulonglong2 vv =
                    *(const ulonglong2*)&A4[(u << 5) | (lane ^ (u & 7))];
                unsigned long long p;
                p = splat2(p4.x); ffma2(oAcc[0][0], vv.x, p); ffma2(oAcc[0][1], vv.y, p);
                p = splat2(p4.y); ffma2(oAcc[1][0], vv.x, p); ffma2(oAcc[1][1], vv.y, p);
                p = splat2(p4.z); ffma2(oAcc[2][0], vv.x, p); ffma2(oAcc[2][1], vv.y, p);
                p = splat2(p4.w); ffma2(oAcc[3][0], vv.x, p); ffma2(oAcc[3][1], vv.y, p);
            }
        }

        // ---- phase 4: wait V.1 (B); issue K.0_{s+1} -> A; PV.1 ----
        asm volatile("cp.async.wait_group 0;");
        __syncthreads();
        if (s + 1 < SSEL)
            loadHalf(A4, k + ((size_t)(nidx*BS)*HKV + h) * DIM);
        {
            #pragma unroll 4
            for (int u = 32; u < 64; ++u) {
                const float4 p4 = Pw[u];
                const ulonglong2 vv =
                    *(const ulonglong2*)&B4[((u & 31) << 5) | (lane ^ (u & 7))];
                unsigned long long p;
                p = splat2(p4.x); ffma2(oAcc[0][0], vv.x, p); ffma2(oAcc[0][1], vv.y, p);
                p = splat2(p4.y); ffma2(oAcc[1][0], vv.x, p); ffma2(oAcc[1][1], vv.y, p);
                p = splat2(p4.z); ffma2(oAcc[2][0], vv.x, p); ffma2(oAcc[2][1], vv.y, p);
                p = splat2(p4.w); ffma2(oAcc[3][0], vv.x, p); ffma2(oAcc[3][1], vv.y, p);
            }
        }
    }

    // ---- write output ----
    #pragma unroll
    for (int g = 0; g < 4; ++g) {
        const float2 lo = unpack2(oAcc[g][0]);
        const float2 hi = unpack2(oAcc[g][1]);
        float4* op = (float4*)(out + ((size_t)l*HQN + h*GPH + 4*wid + g) * DIM);
        op[lane] = make_float4(lo.x, lo.y, hi.x, hi.y);
    }
}

extern "C" void kernel_launch(void* const* d_in, const int* in_sizes, int n_in,
                              void* d_out, int out_size)
{
    (void)in_sizes; (void)n_in; (void)out_size;
    const float* q    = (const float*)d_in[0];
    const float* k    = (const float*)d_in[1];
    const float* v    = (const float*)d_in[2];
    const float* w    = (const float*)d_in[3];
    const int*   bidx = (const int*)d_in[4];
    float* out = (float*)d_out;

    static bool attr_set = false;
    if (!attr_set) {
        cudaFuncSetAttribute(hsa_prefill_kernel,
                             cudaFuncAttributeMaxDynamicSharedMemorySize, SMEM_BYTES);
        attr_set = true;
    }

    dim3 grid(LQ * HKV);
    dim3 block(NTHREADS);
    hsa_prefill_kernel<<<grid, block, SMEM_BYTES>>>(q, k, v, w, bidx, out);
}